// round 4
// baseline (speedup 1.0000x reference)
#include <cuda_runtime.h>
#include <math_constants.h>

// Problem constants (fixed by setup_inputs)
#define N1T   65536
#define N2T   16384
#define CIN   512
#define COUT  256
#define BN_EPS 1e-5f

// Scratch (device globals: no allocation allowed in kernel_launch)
__device__ float g_f2[N2T * COUT];        // 16 MB, stays L2-resident
__device__ int   g_knn_idx[N1T * 3];
__device__ float g_knn_w[N1T * 3];

// ---------------------------------------------------------------------------
// KNN: one thread per query; segment points staged through SMEM in chunks.
// d2 arithmetic replicates the reference bit pattern:
//   qq = (qx*qx + qy*qy) + qz*qz            (rounded mul, sequential adds)
//   pp = (px*px + py*py) + pz*pz
//   dot = fma(qz,pz, fma(qy,py, qx*px))     (k-ascending FFMA GEMM chain)
//   d2  = (qq + pp) - 2*dot                 (2*dot exact; single subtract)
// Strict-< insertion keeps lower index on ties (matches jax.lax.top_k).
// ---------------------------------------------------------------------------
#define KNN_CHUNK 2048

__global__ void knn_kernel(const float* __restrict__ pts1,
                           const int*   __restrict__ rs1,
                           const float* __restrict__ pts2,
                           const int*   __restrict__ rs2) {
    __shared__ float4 sp[KNN_CHUNK];

    const int seg = blockIdx.y;
    const int tid = threadIdx.x;
    const int q_start = rs1[seg], q_end = rs1[seg + 1];
    const int p_start = rs2[seg], p_end = rs2[seg + 1];
    const int nq = q_end - q_start;
    const int np = p_end - p_start;

    const int ql = blockIdx.x * blockDim.x + tid;
    const bool active = ql < nq;
    const int q = q_start + (active ? ql : 0);

    const float qx = pts1[q * 3 + 0];
    const float qy = pts1[q * 3 + 1];
    const float qz = pts1[q * 3 + 2];
    // qq with explicit rounding (matches jnp.sum(q*q, axis=1))
    const float qq = __fadd_rn(__fadd_rn(__fmul_rn(qx, qx), __fmul_rn(qy, qy)),
                               __fmul_rn(qz, qz));

    float d0 = CUDART_INF_F, d1 = CUDART_INF_F, d2 = CUDART_INF_F;
    int   i0 = 0, i1 = 0, i2 = 0;

    for (int cb = 0; cb < np; cb += KNN_CHUNK) {
        const int cnt = min(KNN_CHUNK, np - cb);
        __syncthreads();
        for (int j = tid; j < cnt; j += blockDim.x) {
            const int pi = p_start + cb + j;
            const float px = pts2[pi * 3 + 0];
            const float py = pts2[pi * 3 + 1];
            const float pz = pts2[pi * 3 + 2];
            const float pp = __fadd_rn(
                __fadd_rn(__fmul_rn(px, px), __fmul_rn(py, py)),
                __fmul_rn(pz, pz));
            sp[j] = make_float4(px, py, pz, pp);
        }
        __syncthreads();
        if (active) {
            #pragma unroll 4
            for (int j = 0; j < cnt; ++j) {
                const float4 p = sp[j];
                // dot in cuBLAS k-ascending FFMA order
                const float dot = fmaf(qz, p.z,
                                       fmaf(qy, p.y, __fmul_rn(qx, p.x)));
                const float t = __fsub_rn(__fadd_rn(qq, p.w),
                                          __fmul_rn(2.0f, dot));
                if (t < d2) {                 // rare branch: ~3*ln(np) hits
                    const int gj = cb + j;
                    if (t < d1) {
                        d2 = d1; i2 = i1;
                        if (t < d0) { d1 = d0; i1 = i0; d0 = t; i0 = gj; }
                        else        { d1 = t;  i1 = gj; }
                    } else { d2 = t; i2 = gj; }
                }
            }
        }
    }

    if (active) {
        const float e0 = fmaxf(d0, 0.f), e1 = fmaxf(d1, 0.f), e2 = fmaxf(d2, 0.f);
        const float w0 = 1.f / (e0 + 1e-8f);
        const float w1 = 1.f / (e1 + 1e-8f);
        const float w2 = 1.f / (e2 + 1e-8f);
        const float inv = 1.f / (w0 + w1 + w2);
        const int base = q * 3;
        g_knn_idx[base + 0] = p_start + i0;  g_knn_w[base + 0] = w0 * inv;
        g_knn_idx[base + 1] = p_start + i1;  g_knn_w[base + 1] = w1 * inv;
        g_knn_idx[base + 2] = p_start + i2;  g_knn_w[base + 2] = w2 * inv;
    }
}

// ---------------------------------------------------------------------------
// Tiled SGEMM:  out[m][c] = relu( (X[m,:] . W[c,:] + b[c] - mean[c])*scale + beta )
//               (+ optional 3-NN interp gather from g_f2)
// BM=128, BN=64, BK=16, 256 threads, 8x4 per thread.
// ---------------------------------------------------------------------------
template <int KD, bool INTERP>
__global__ void __launch_bounds__(256)
gemm_bn_relu_kernel(const float* __restrict__ X,
                    const float* __restrict__ W,
                    const float* __restrict__ bb,
                    const float* __restrict__ gg,
                    const float* __restrict__ be,
                    const float* __restrict__ mm,
                    const float* __restrict__ vv,
                    float* __restrict__ out) {
    constexpr int BM = 128, BN = 64, BK = 16;
    __shared__ float As[BK][BM];   // k-major
    __shared__ float Bs[BK][BN];   // k-major

    const int tid = threadIdx.x;
    const int m0 = blockIdx.x * BM;
    const int c0 = blockIdx.y * BN;
    const int tx = tid & 15;       // 16 col groups of 4
    const int ty = tid >> 4;       // 16 row groups of 8

    float acc[8][4];
    #pragma unroll
    for (int i = 0; i < 8; ++i)
        #pragma unroll
        for (int j = 0; j < 4; ++j) acc[i][j] = 0.f;

    for (int k0 = 0; k0 < KD; k0 += BK) {
        // Load A tile: 512 float4 (128 rows x 16 k), 2 per thread
        #pragma unroll
        for (int r = 0; r < 2; ++r) {
            const int f = tid + r * 256;
            const int m = f >> 2;
            const int k = (f & 3) * 4;
            const float4 va = *reinterpret_cast<const float4*>(
                &X[(size_t)(m0 + m) * KD + k0 + k]);
            As[k + 0][m] = va.x; As[k + 1][m] = va.y;
            As[k + 2][m] = va.z; As[k + 3][m] = va.w;
        }
        // Load B tile (= W^T): 256 float4 (64 cols x 16 k), 1 per thread
        {
            const int c = tid >> 2;
            const int k = (tid & 3) * 4;
            const float4 vb = *reinterpret_cast<const float4*>(
                &W[(size_t)(c0 + c) * KD + k0 + k]);
            Bs[k + 0][c] = vb.x; Bs[k + 1][c] = vb.y;
            Bs[k + 2][c] = vb.z; Bs[k + 3][c] = vb.w;
        }
        __syncthreads();

        #pragma unroll
        for (int k = 0; k < BK; ++k) {
            const float4 a0 = *reinterpret_cast<const float4*>(&As[k][ty * 8 + 0]);
            const float4 a1 = *reinterpret_cast<const float4*>(&As[k][ty * 8 + 4]);
            const float4 b0 = *reinterpret_cast<const float4*>(&Bs[k][tx * 4]);
            const float ar[8] = {a0.x, a0.y, a0.z, a0.w, a1.x, a1.y, a1.z, a1.w};
            const float br[4] = {b0.x, b0.y, b0.z, b0.w};
            #pragma unroll
            for (int i = 0; i < 8; ++i)
                #pragma unroll
                for (int j = 0; j < 4; ++j)
                    acc[i][j] = fmaf(ar[i], br[j], acc[i][j]);
        }
        __syncthreads();
    }

    // Epilogue: BN(eval) + ReLU (+ interp gather)
    const int c = c0 + tx * 4;
    const float4 bv  = *reinterpret_cast<const float4*>(&bb[c]);
    const float4 gv  = *reinterpret_cast<const float4*>(&gg[c]);
    const float4 bev = *reinterpret_cast<const float4*>(&be[c]);
    const float4 mv  = *reinterpret_cast<const float4*>(&mm[c]);
    const float4 vvv = *reinterpret_cast<const float4*>(&vv[c]);

    float sc[4], sh[4];
    sc[0] = gv.x * rsqrtf(vvv.x + BN_EPS); sh[0] = (bv.x - mv.x) * sc[0] + bev.x;
    sc[1] = gv.y * rsqrtf(vvv.y + BN_EPS); sh[1] = (bv.y - mv.y) * sc[1] + bev.y;
    sc[2] = gv.z * rsqrtf(vvv.z + BN_EPS); sh[2] = (bv.z - mv.z) * sc[2] + bev.z;
    sc[3] = gv.w * rsqrtf(vvv.w + BN_EPS); sh[3] = (bv.w - mv.w) * sc[3] + bev.w;

    #pragma unroll
    for (int i = 0; i < 8; ++i) {
        const int r = m0 + ty * 8 + i;
        float4 o;
        o.x = fmaxf(fmaf(acc[i][0], sc[0], sh[0]), 0.f);
        o.y = fmaxf(fmaf(acc[i][1], sc[1], sh[1]), 0.f);
        o.z = fmaxf(fmaf(acc[i][2], sc[2], sh[2]), 0.f);
        o.w = fmaxf(fmaf(acc[i][3], sc[3], sh[3]), 0.f);
        if (INTERP) {
            const int b3 = r * 3;
            const int j0 = g_knn_idx[b3 + 0];
            const int j1 = g_knn_idx[b3 + 1];
            const int j2 = g_knn_idx[b3 + 2];
            const float w0 = g_knn_w[b3 + 0];
            const float w1 = g_knn_w[b3 + 1];
            const float w2 = g_knn_w[b3 + 2];
            const float4 f0 = *reinterpret_cast<const float4*>(&g_f2[(size_t)j0 * COUT + c]);
            const float4 f1 = *reinterpret_cast<const float4*>(&g_f2[(size_t)j1 * COUT + c]);
            const float4 f2 = *reinterpret_cast<const float4*>(&g_f2[(size_t)j2 * COUT + c]);
            o.x += w0 * f0.x + w1 * f1.x + w2 * f2.x;
            o.y += w0 * f0.y + w1 * f1.y + w2 * f2.y;
            o.z += w0 * f0.z + w1 * f1.z + w2 * f2.z;
            o.w += w0 * f0.w + w1 * f1.w + w2 * f2.w;
        }
        *reinterpret_cast<float4*>(&out[(size_t)r * COUT + c]) = o;
    }
}

// ---------------------------------------------------------------------------
extern "C" void kernel_launch(void* const* d_in, const int* in_sizes, int n_in,
                              void* d_out, int out_size) {
    const float* points_1 = (const float*)d_in[0];
    const float* feat_1   = (const float*)d_in[1];
    const int*   rs1      = (const int*)  d_in[2];
    const float* points_2 = (const float*)d_in[3];
    const float* feat_2   = (const float*)d_in[4];
    const int*   rs2      = (const int*)  d_in[5];
    const float* w1  = (const float*)d_in[6];
    const float* b1  = (const float*)d_in[7];
    const float* g1  = (const float*)d_in[8];
    const float* be1 = (const float*)d_in[9];
    const float* m1  = (const float*)d_in[10];
    const float* v1  = (const float*)d_in[11];
    const float* w2  = (const float*)d_in[12];
    const float* b2  = (const float*)d_in[13];
    const float* g2  = (const float*)d_in[14];
    const float* be2 = (const float*)d_in[15];
    const float* m2  = (const float*)d_in[16];
    const float* v2  = (const float*)d_in[17];
    float* out = (float*)d_out;

    float* f2_ptr;
    cudaGetSymbolAddress((void**)&f2_ptr, g_f2);

    // 1) f2 = relu(BN(feat_2 @ w2.T + b2))   -> g_f2
    {
        dim3 grid(N2T / 128, COUT / 64);
        gemm_bn_relu_kernel<CIN, false><<<grid, 256>>>(
            feat_2, w2, b2, g2, be2, m2, v2, f2_ptr);
    }
    // 2) per-segment 3-NN (indep. of f2 values; ordering on stream is fine)
    {
        dim3 grid((N1T + 255) / 256, 4);
        knn_kernel<<<grid, 256>>>(points_1, rs1, points_2, rs2);
    }
    // 3) out = relu(BN(feat_1 @ w1.T + b1)) + interp
    {
        dim3 grid(N1T / 128, COUT / 64);
        gemm_bn_relu_kernel<COUT, true><<<grid, 256>>>(
            feat_1, w1, b1, g1, be1, m1, v1, out);
    }
}